// round 13
// baseline (speedup 1.0000x reference)
#include <cuda_runtime.h>
#include <cooperative_groups.h>
#include <math.h>

namespace cg = cooperative_groups;

#define EPS 1e-8f
typedef unsigned long long u64;
// B=64, S=64, I=64, O=64, N=1024, M=64, H=256, 4H=1024, P=268
// Round 13 = round-8 skeleton + cross-step pipelined gate GEMM:
// the x+h part (320/384 K-rows) of NEXT step's gates is computed in THIS step's
// S3 shadow into gpart; at step top only the r-part (64 rows) is added.
// Also: key norms folded into the parse barrier region (one less phase/barrier).

__device__ float g_W[384 * 1024];   // rows 0..127 = Wx, 128..383 = Wh

struct __align__(16) SMem {
    float  mem[64 * 512];     // own batch's memory half, [m][nl] (128 KB)
    float4 part[2048];        // scratch partials (32 KB), region-multiplexed
    ulonglong2 gpart[2048];   // pipelined gate partials (32 KB): [0,1024)=A, [1024,2048)=B
    float  wr[512], ww[512];  // unnormalized wp mid-step, normalized post-S45
    float  t1[512], t2[512];
    float2 vh[768];           // bank0: [0,64)x [64,128)r [128,384)h ; bank1: +384
    float2 h2c[256];          // current-step full h pairs {hA, hB}
    float2 h2own[64];         // own h quarter pairs
    float  nnp[512];          // per-n norm (own half)
    float  c[2][64];
    float  gates[2][256];
    float  p[272];            // full head output for OWN batch
    float  ppart[4][272];     // head partials from 4 ranks
    float2 krw[64];           // {kr[m], kw[m]}
    float  e[64], a[64];
    float  rrecv[4][64];
    float2 rvec2[64];
    float  scal[16];
    float  qhalo[4];
    float  wh_r[2], wh_w[2];  // normalized prev-w halos
    float  whp_r[2], whp_w[2];// unnormalized boundary wp from peer
    float  xch[4];            // pair softmax-sum slots
    float2 zrecv[4];          // sharpen sums from all 4 ranks
    float2 red[32];
};

__device__ __forceinline__ float sigmoidf_(float x) { return 1.f / (1.f + expf(-x)); }
__device__ __forceinline__ float softplusf_(float x) { return fmaxf(x, 0.f) + log1pf(expf(-fabsf(x))); }

__device__ __forceinline__ u64 pk2(float a, float b) {
    u64 r; asm("mov.b64 %0, {%1, %2};" : "=l"(r) : "f"(a), "f"(b)); return r;
}
__device__ __forceinline__ float2 up2(u64 v) {
    float2 r; asm("mov.b64 {%0, %1}, %2;" : "=f"(r.x), "=f"(r.y) : "l"(v)); return r;
}
__device__ __forceinline__ void fma2(u64& d, u64 a, u64 b) {
    asm("fma.rn.f32x2 %0, %1, %2, %0;" : "+l"(d) : "l"(a), "l"(b));
}
__device__ __forceinline__ u64 fma2n(u64 a, u64 b, u64 c) {
    u64 d; asm("fma.rn.f32x2 %0, %1, %2, %3;" : "=l"(d) : "l"(a), "l"(b), "l"(c)); return d;
}
__device__ __forceinline__ u64 mul2(u64 a, u64 b) {
    u64 d; asm("mul.rn.f32x2 %0, %1, %2;" : "=l"(d) : "l"(a), "l"(b)); return d;
}
__device__ __forceinline__ u64 add2(u64 a, u64 b) {
    u64 d; asm("add.rn.f32x2 %0, %1, %2;" : "=l"(d) : "l"(a), "l"(b)); return d;
}
#define CL_ARRIVE() asm volatile("barrier.cluster.arrive.aligned;" ::: "memory")
#define CL_WAIT()   asm volatile("barrier.cluster.wait.aligned;"   ::: "memory")

// Single-barrier block sum of a float2 across 1024 threads; result in all threads.
__device__ __forceinline__ float2 blockReduceSum2(float2 v, float2* red) {
#pragma unroll
    for (int o = 16; o; o >>= 1) {
        v.x += __shfl_xor_sync(0xffffffffu, v.x, o);
        v.y += __shfl_xor_sync(0xffffffffu, v.y, o);
    }
    if ((threadIdx.x & 31) == 0) red[threadIdx.x >> 5] = v;
    __syncthreads();
    float2 w = red[threadIdx.x & 31];
#pragma unroll
    for (int o = 16; o; o >>= 1) {
        w.x += __shfl_xor_sync(0xffffffffu, w.x, o);
        w.y += __shfl_xor_sync(0xffffffffu, w.y, o);
    }
    return w;
}

__global__ void __launch_bounds__(1024, 1) __cluster_dims__(4, 1, 1)
ntm_kernel(const float* __restrict__ x,       // (64,64,64)
           const float* __restrict__ b_lstm,  // (1024)
           const float* __restrict__ W_head,  // (256,268)
           const float* __restrict__ b_head,  // (268)
           const float* __restrict__ W_out,   // (320,64)
           const float* __restrict__ b_out,   // (64)
           float* __restrict__ out)           // (64,64,64)
{
    extern __shared__ char smraw[];
    SMem* s = (SMem*)smraw;
    cg::cluster_group cl = cg::this_cluster();

    const int rank = (int)cl.block_rank();
    const int clid = blockIdx.x >> 2;
    const int t    = threadIdx.x;

    SMem* P0 = (SMem*)cl.map_shared_rank(smraw, 0);
    SMem* P1 = (SMem*)cl.map_shared_rank(smraw, 1);
    SMem* P2 = (SMem*)cl.map_shared_rank(smraw, 2);
    SMem* P3 = (SMem*)cl.map_shared_rank(smraw, 3);
    SMem* PP[4] = {P0, P1, P2, P3};
    SMem* pp = (SMem*)cl.map_shared_rank(smraw, rank ^ 1);   // pair peer

    float*      partf = (float*)s->part;
    float2*     part2 = (float2*)s->part;
    ulonglong2* partq = (ulonglong2*)s->part;
    float4*     mem4  = (float4*)s->mem;
    ulonglong2* memq  = (ulonglong2*)s->mem;

    const int bgA = clid * 2, bgB = clid * 2 + 1;

    // Gate-GEMM thread constants (shared by phase A / phase B)
    const int gqi = t & 63, gch = t >> 6;
    const int gcol4 = (gqi >> 4) * 64 + rank * 16 + (gqi & 15);

    // Hoisted out-GEMM constants
    const int jc8 = t & 15, ch8 = t >> 4;
    const int col8 = rank * 16 + jc8;
    float4 w8a;
    {
        int r0 = ch8 * 4;
        w8a = make_float4(W_out[(r0 + 0) * 64 + col8], W_out[(r0 + 1) * 64 + col8],
                          W_out[(r0 + 2) * 64 + col8], W_out[(r0 + 3) * 64 + col8]);
    }
    const float w8b = W_out[(256 + ch8) * 64 + col8];
    const float bo  = (t < 16) ? b_out[rank * 16 + t] : 0.f;

    // ---- init ----
    {
        float4 iv = make_float4(0.01f, 0.01f, 0.01f, 0.01f);
#pragma unroll
        for (int i = 0; i < 8; ++i) mem4[i * 1024 + t] = iv;
        if (t < 512) { float w0 = ((rank & 1) == 0 && t == 0) ? 1.f : 0.f; s->wr[t] = w0; s->ww[t] = w0; }
        if (t < 768) s->vh[t] = make_float2(0.f, 0.f);
        if (t < 256) s->h2c[t] = make_float2(0.f, 0.f);
        if (t < 128) ((float*)s->c)[t] = 0.f;
        if (t < 64)  { s->rvec2[t] = make_float2(0.f, 0.f); s->h2own[t] = make_float2(0.f, 0.f);
                       s->e[t] = 0.f; s->a[t] = 0.f; }   // step-0 deferred update = identity
        if (t < 64) {
            float2 xv = make_float2(x[(bgA << 6) * 64 + t], x[(bgB << 6) * 64 + t]);
            s->vh[t] = xv; s->vh[384 + t] = xv;
        }
        if (t == 0) {
            float hv = (rank & 1) ? 1.f : 0.f;
            s->wh_r[0] = hv; s->wh_w[0] = hv;
            s->wh_r[1] = 0.f; s->wh_w[1] = 0.f;
        }
    }
    __syncthreads();
    // ---- init phase-B: x+h gate partials for step 0 (bank 0; h = 0, x = x(0)) ----
    {
        const ulonglong2* gw2 = (const ulonglong2*)g_W;
        const float2* vrow = s->vh;
        u64 aA01 = 0ull, aA23 = 0ull, aB01 = 0ull, aB23 = 0ull;
        int i0 = gch * 20;
#pragma unroll 4
        for (int i = i0; i < i0 + 20; ++i) {
            int rr = (i < 64) ? i : i + 64;
            ulonglong2 w2 = gw2[rr * 256 + gcol4];
            float2 vv = vrow[rr];
            u64 vA2 = pk2(vv.x, vv.x), vB2 = pk2(vv.y, vv.y);
            fma2(aA01, w2.x, vA2); fma2(aA23, w2.y, vA2);
            fma2(aB01, w2.x, vB2); fma2(aB23, w2.y, vB2);
        }
        ulonglong2 sa; sa.x = aA01; sa.y = aA23;
        ulonglong2 sb; sb.x = aB01; sb.y = aB23;
        s->gpart[t] = sa;
        s->gpart[1024 + t] = sb;
    }
    cl.sync();

    float2 xpref = make_float2(0.f, 0.f);

    for (int step = 0; step < 64; ++step) {
        const int prv = step & 1, cur = prv ^ 1;

        // ---- top: prefetch next x (threads 128-191, held in regs all step) ----
        if (t >= 128 && t < 192) {
            int idx = t - 128;
            int sn = (step < 63) ? step + 1 : 63;
            xpref = make_float2(x[((bgA << 6) + sn) * 64 + idx],
                                x[((bgB << 6) + sn) * 64 + idx]);
        }

        // ---- phase A: add r-part (4 rows) onto pipelined gate partials ----
        {
            const ulonglong2* gw2 = (const ulonglong2*)g_W;
            const float2* vrow = s->vh + prv * 384;
            ulonglong2 ga = s->gpart[t], gb = s->gpart[1024 + t];
            u64 aA01 = ga.x, aA23 = ga.y, aB01 = gb.x, aB23 = gb.y;
            int r0 = 64 + gch * 4;
#pragma unroll
            for (int rr = r0; rr < r0 + 4; ++rr) {
                ulonglong2 w2 = gw2[rr * 256 + gcol4];
                float2 vv = vrow[rr];
                u64 vA2 = pk2(vv.x, vv.x), vB2 = pk2(vv.y, vv.y);
                fma2(aA01, w2.x, vA2); fma2(aA23, w2.y, vA2);
                fma2(aB01, w2.x, vB2); fma2(aB23, w2.y, vB2);
            }
            ulonglong2 sa; sa.x = aA01; sa.y = aA23;
            ulonglong2 sb; sb.x = aB01; sb.y = aB23;
            partq[t] = sa;
            partq[1024 + t] = sb;
        }
        __syncthreads();
        if (t < 128) {
            int bat = t >> 6, qi = t & 63;
            int qb = qi >> 4, qw = qi & 15;
            int col4 = qb * 64 + rank * 16 + qw;
            ulonglong2 bb = ((const ulonglong2*)b_lstm)[col4];
            u64 a01 = bb.x, a23 = bb.y;
#pragma unroll
            for (int ch = 0; ch < 16; ++ch) {
                ulonglong2 pc = partq[bat * 1024 + ch * 64 + qi];
                a01 = add2(a01, pc.x); a23 = add2(a23, pc.y);
            }
            ulonglong2 g; g.x = a01; g.y = a23;
            ((ulonglong2*)s->gates[bat])[qi] = g;
        }
        __syncthreads();

        // ---- LSTM pointwise; broadcast h; stage next x into both banks ----
        if (t < 128) {
            int bat = t >> 6, jl = t & 63;
            float ig = s->gates[bat][jl],       fg = s->gates[bat][64 + jl],
                  gg = s->gates[bat][128 + jl], og = s->gates[bat][192 + jl];
            float cc = sigmoidf_(fg) * s->c[bat][jl] + sigmoidf_(ig) * tanhf(gg);
            s->c[bat][jl] = cc;
            float hv = sigmoidf_(og) * tanhf(cc);
            int gj = rank * 64 + jl;
            ((float*)&s->h2own[jl])[bat] = hv;
#pragma unroll
            for (int i = 0; i < 4; ++i) {
                ((float*)&PP[i]->vh[128 + cur * 384 + gj])[bat] = hv;
                ((float*)&PP[i]->h2c[gj])[bat] = hv;
            }
        } else if (t < 192) {
            int idx = t - 128;
            s->vh[idx] = xpref;          // x(s+1) into both banks (local)
            s->vh[384 + idx] = xpref;
        }
        __syncthreads();

        // ---- head PARTIAL GEMM from own h quarter ----
        if (t < 536) {
            int half = t / 268, j = t - half * 268;
            const float* whp = W_head + (64 * rank + half * 32) * 268 + j;
            u64 acc = 0ull;
#pragma unroll 8
            for (int k = 0; k < 32; ++k) {
                float w = whp[k * 268];
                u64 hv = *(const u64*)(s->h2own + half * 32 + k);
                fma2(acc, hv, pk2(w, w));
            }
            part2[t] = up2(acc);
        }
        __syncthreads();
        if (t < 268) {
            float2 pa = part2[t], pb = part2[t + 268];
            float vx = pa.x + pb.x, vy = pa.y + pb.y;
            P0->ppart[rank][t] = vx; P1->ppart[rank][t] = vx;
            P2->ppart[rank][t] = vy; P3->ppart[rank][t] = vy;
        }
        CL_ARRIVE();   // S1 arrive
        // ---- S1 shadow: DEFERRED memory update (prev ww,e,a) + norm accumulation ----
        {
            int n4 = t & 127, mch = t >> 7;
            ulonglong2 ww2 = ((const ulonglong2*)s->ww)[n4];
            const u64 one2 = pk2(1.f, 1.f);
            u64 nn01 = 0ull, nn23 = 0ull;
#pragma unroll 4
            for (int mi = 0; mi < 8; ++mi) {
                int m = mch * 8 + mi;
                float em = s->e[m], am = s->a[m];
                u64 nem2 = pk2(-em, -em), am2 = pk2(am, am);
                ulonglong2 v2 = memq[m * 128 + n4];
                v2.x = fma2n(v2.x, fma2n(ww2.x, nem2, one2), mul2(ww2.x, am2));
                v2.y = fma2n(v2.y, fma2n(ww2.y, nem2, one2), mul2(ww2.y, am2));
                memq[m * 128 + n4] = v2;
                fma2(nn01, v2.x, v2.x); fma2(nn23, v2.y, v2.y);
            }
            ulonglong2 nnq; nnq.x = nn01; nnq.y = nn23;
            ((ulonglong2*)s->part)[1024 + mch * 128 + n4] = nnq;
        }
        CL_WAIT();     // S1: full h + head partials everywhere
        __syncthreads();   // order shadow writes intra-CTA

        // ---- post-S1: sum head partials (own batch) + reduce norms ----
        if (t < 268) {
            s->p[t] = s->ppart[0][t] + s->ppart[1][t] + s->ppart[2][t] + s->ppart[3][t]
                    + b_head[t];
        } else if (t >= 512) {
            int nl0 = t - 512;
            float nn = 0.f;
#pragma unroll
            for (int mch = 0; mch < 8; ++mch) nn += partf[4096 + mch * 512 + nl0];
            s->nnp[nl0] = nn;
        }
        __syncthreads();

        // ---- parse heads + key norms (folded, warps 10-11) ----
        if (t < 64) s->krw[t].x = tanhf(s->p[t]);
        else if (t < 128) s->krw[t - 64].y = tanhf(s->p[70 + t - 64]);
        else if (t < 192) s->e[t - 128] = sigmoidf_(s->p[140 + (t - 128)]);
        else if (t < 256) s->a[t - 192] = s->p[204 + (t - 192)];
        else if (t == 256) {
            s->scal[0] = softplusf_(s->p[64]);
            s->scal[1] = sigmoidf_(s->p[65]);
            float a0 = s->p[66], a1 = s->p[67], a2 = s->p[68];
            float mx = fmaxf(a0, fmaxf(a1, a2));
            float e0 = expf(a0 - mx), e1 = expf(a1 - mx), e2 = expf(a2 - mx);
            float sm = e0 + e1 + e2;
            s->scal[2] = e0 / sm; s->scal[3] = e1 / sm; s->scal[4] = e2 / sm;
            s->scal[5] = 1.f + softplusf_(s->p[69]);
        } else if (t == 288) {
            s->scal[8] = softplusf_(s->p[134]);
            s->scal[9] = sigmoidf_(s->p[135]);
            float a0 = s->p[136], a1 = s->p[137], a2 = s->p[138];
            float mx = fmaxf(a0, fmaxf(a1, a2));
            float e0 = expf(a0 - mx), e1 = expf(a1 - mx), e2 = expf(a2 - mx);
            float sm = e0 + e1 + e2;
            s->scal[10] = e0 / sm; s->scal[11] = e1 / sm; s->scal[12] = e2 / sm;
            s->scal[13] = 1.f + softplusf_(s->p[139]);
        } else if (t >= 320 && t < 352) {
            int l = t - 320;
            float k0 = tanhf(s->p[l]), k1 = tanhf(s->p[l + 32]);
            float v = k0 * k0 + k1 * k1;
#pragma unroll
            for (int o = 16; o; o >>= 1) v += __shfl_xor_sync(0xffffffffu, v, o);
            if (l == 0) s->scal[6] = sqrtf(v);
        } else if (t >= 352 && t < 384) {
            int l = t - 352;
            float k0 = tanhf(s->p[70 + l]), k1 = tanhf(s->p[70 + l + 32]);
            float v = k0 * k0 + k1 * k1;
#pragma unroll
            for (int o = 16; o; o >>= 1) v += __shfl_xor_sync(0xffffffffu, v, o);
            if (l == 0) s->scal[7] = sqrtf(v);
        }
        __syncthreads();

        // ---- addressing dots over own 512 n-rows (updated mem), packed ----
        const int nl = t & 511, mh = t >> 9;
        {
            u64 drw = 0ull;
            int m0 = mh * 32;
#pragma unroll 8
            for (int m = m0; m < m0 + 32; ++m) {
                float v = s->mem[m * 512 + nl];
                u64 kv = *(const u64*)(s->krw + m);
                fma2(drw, kv, pk2(v, v));
            }
            float2 d = up2(drw);
            s->part[t] = make_float4(d.x, d.y, 0.f, 0.f);
        }
        __syncthreads();
        const bool lead = (t < 512);
        float qr = 0.f, qw = 0.f, er = 0.f, ew = 0.f;
        if (lead) {
            float4 p0 = s->part[t], p1 = s->part[t + 512];
            float dr = p0.x + p1.x, dw = p0.y + p1.y;
            float nrm = sqrtf(s->nnp[nl]);
            qr = s->scal[0] * (dr / (s->scal[6] * nrm + EPS));
            qw = s->scal[8] * (dw / (s->scal[7] * nrm + EPS));
            if (nl == 0)   { pp->qhalo[0] = qr; pp->qhalo[2] = qw; }
            if (nl == 511) { pp->qhalo[1] = qr; pp->qhalo[3] = qw; }
            er = expf(qr);
            ew = expf(qw);
        }
        float2 lsum = blockReduceSum2(make_float2(er, ew), s->red);
        if (t == 0) { pp->xch[0] = lsum.x; pp->xch[1] = lsum.y; }
        CL_ARRIVE();   // S3 arrive
        // ---- S3 shadow: out-GEMM h-part + PIPELINED next-gates x+h part ----
        {
            const float* hb = (const float*)s->h2c;
            int r0 = ch8 * 4;
            u64 acc = 0ull;
            u64 h0 = *(const u64*)(hb + 2 * (r0 + 0));
            u64 h1 = *(const u64*)(hb + 2 * (r0 + 1));
            u64 h2 = *(const u64*)(hb + 2 * (r0 + 2));
            u64 h3 = *(const u64*)(hb + 2 * (r0 + 3));
            fma2(acc, h0, pk2(w8a.x, w8a.x));
            fma2(acc, h1, pk2(w8a.y, w8a.y));
            fma2(acc, h2, pk2(w8a.z, w8a.z));
            fma2(acc, h3, pk2(w8a.w, w8a.w));
            part2[3072 + t] = up2(acc);
        }
        {
            const ulonglong2* gw2 = (const ulonglong2*)g_W;
            const float2* vrow = s->vh + cur * 384;   // next step's input bank (x+h valid)
            u64 aA01 = 0ull, aA23 = 0ull, aB01 = 0ull, aB23 = 0ull;
            int i0 = gch * 20;
#pragma unroll 4
            for (int i = i0; i < i0 + 20; ++i) {
                int rr = (i < 64) ? i : i + 64;
                ulonglong2 w2 = gw2[rr * 256 + gcol4];
                float2 vv = vrow[rr];
                u64 vA2 = pk2(vv.x, vv.x), vB2 = pk2(vv.y, vv.y);
                fma2(aA01, w2.x, vA2); fma2(aA23, w2.y, vA2);
                fma2(aB01, w2.x, vB2); fma2(aB23, w2.y, vB2);
            }
            ulonglong2 sa; sa.x = aA01; sa.y = aA23;
            ulonglong2 sb; sb.x = aB01; sb.y = aB23;
            s->gpart[t] = sa;
            s->gpart[1024 + t] = sb;
        }
        CL_WAIT();     // S3: pair softmax sums + boundary q
        const float gsr = lsum.x + s->xch[0];
        const float gsw = lsum.y + s->xch[1];
        const float g_r = s->scal[1], g_w = s->scal[9];
        if (lead) {
            float wgr = g_r * (er / gsr) + (1.f - g_r) * s->wr[nl];
            float wgw = g_w * (ew / gsw) + (1.f - g_w) * s->ww[nl];
            s->t1[nl] = wgr;
            s->t2[nl] = wgw;
        }
        __syncthreads();
        float wpr = 0.f, wpw = 0.f;
        if (lead) {
            float t1p = (nl == 511) ? (g_r * (expf(s->qhalo[0]) / gsr) + (1.f - g_r) * s->wh_r[0]) : s->t1[nl + 1];
            float t1m = (nl == 0)   ? (g_r * (expf(s->qhalo[1]) / gsr) + (1.f - g_r) * s->wh_r[1]) : s->t1[nl - 1];
            float t2p = (nl == 511) ? (g_w * (expf(s->qhalo[2]) / gsw) + (1.f - g_w) * s->wh_w[0]) : s->t2[nl + 1];
            float t2m = (nl == 0)   ? (g_w * (expf(s->qhalo[3]) / gsw) + (1.f - g_w) * s->wh_w[1]) : s->t2[nl - 1];
            float wsr = s->scal[2]  * t1p + s->scal[3]  * s->t1[nl] + s->scal[4]  * t1m;
            float wsw = s->scal[10] * t2p + s->scal[11] * s->t2[nl] + s->scal[12] * t2m;
            wpr = (wsr > 0.f) ? expf(s->scal[5]  * logf(wsr)) : 0.f;
            wpw = (wsw > 0.f) ? expf(s->scal[13] * logf(wsw)) : 0.f;
            s->wr[nl] = wpr;      // UNNORMALIZED until post-S45
            s->ww[nl] = wpw;
            if (nl == 0)   { pp->whp_r[0] = wpr; pp->whp_w[0] = wpw; }
            if (nl == 511) { pp->whp_r[1] = wpr; pp->whp_w[1] = wpw; }
        }
        float2 lsp = blockReduceSum2(make_float2(wpr, wpw), s->red);  // bar publishes s->wr

        // ---- read pass with UNNORMALIZED wr ----
        {
            int n4 = t & 127, mch = t >> 7, wid = t >> 5;
            ulonglong2 wr2 = ((const ulonglong2*)s->wr)[n4];
#pragma unroll 4
            for (int mi = 0; mi < 8; ++mi) {
                int m = mch * 8 + mi;
                ulonglong2 v2 = memq[m * 128 + n4];
                u64 rp2 = 0ull;
                fma2(rp2, wr2.x, v2.x); fma2(rp2, wr2.y, v2.y);
                float2 rr = up2(rp2);
                float rp = rr.x + rr.y;
#pragma unroll
                for (int o = 16; o; o >>= 1) rp += __shfl_xor_sync(0xffffffffu, rp, o);
                if ((t & 31) == 0) partf[2048 + wid * 8 + mi] = rp;
            }
        }
        __syncthreads();
        if (t < 64) {
            int grp = t >> 3, mi = t & 7;
            float v = partf[2048 + (grp * 4 + 0) * 8 + mi]
                    + partf[2048 + (grp * 4 + 1) * 8 + mi]
                    + partf[2048 + (grp * 4 + 2) * 8 + mi]
                    + partf[2048 + (grp * 4 + 3) * 8 + mi];
#pragma unroll
            for (int i = 0; i < 4; ++i) PP[i]->rrecv[rank][t] = v;
        }
        if (t == 0) {
#pragma unroll
            for (int i = 0; i < 4; ++i) PP[i]->zrecv[rank] = lsp;
        }
        CL_ARRIVE();   // S45 arrive
        CL_WAIT();     // S45: sharpen sums + r partials + boundary wp

        // ---- post-S45: normalize, assemble r, stage r into both banks ----
        {
            float2 z0 = s->zrecv[0], z1 = s->zrecv[1], z2 = s->zrecv[2], z3 = s->zrecv[3];
            float invZrA = 1.f / ((z0.x + z1.x) + EPS), invZwA = 1.f / ((z0.y + z1.y) + EPS);
            float invZrB = 1.f / ((z2.x + z3.x) + EPS), invZwB = 1.f / ((z2.y + z3.y) + EPS);
            float invZr = (rank < 2) ? invZrA : invZrB;
            float invZw = (rank < 2) ? invZwA : invZwB;
            if (lead) { s->wr[nl] *= invZr; s->ww[nl] *= invZw; }
            if (t == 0) {
                s->wh_r[0] = s->whp_r[0] * invZr; s->wh_r[1] = s->whp_r[1] * invZr;
                s->wh_w[0] = s->whp_w[0] * invZw; s->wh_w[1] = s->whp_w[1] * invZw;
            }
            if (t < 64) {
                float2 rv = make_float2((s->rrecv[0][t] + s->rrecv[1][t]) * invZrA,
                                        (s->rrecv[2][t] + s->rrecv[3][t]) * invZrB);
                s->rvec2[t] = rv;
                s->vh[64 + t] = rv;
                s->vh[448 + t] = rv;
            }
        }
        __syncthreads();

        // ---- out: add r-part, reduce, write ----
        {
            float2 rv = s->rvec2[ch8];
            float2 pv = part2[3072 + t];
            pv.x += rv.x * w8b; pv.y += rv.y * w8b;
            part2[3072 + t] = pv;
        }
        __syncthreads();
        if (t < 128) {
            int jc = t & 15, g = t >> 4;
            float2 acc = make_float2(0.f, 0.f);
#pragma unroll
            for (int k = 0; k < 8; ++k) {
                float2 pv = part2[3072 + (g * 8 + k) * 16 + jc];
                acc.x += pv.x; acc.y += pv.y;
            }
            part2[t] = acc;
        }
        __syncthreads();
        if (t < 16) {
            float2 acc = make_float2(bo, bo);
#pragma unroll
            for (int g = 0; g < 8; ++g) {
                float2 pv = part2[g * 16 + t];
                acc.x += pv.x; acc.y += pv.y;
            }
            int col = rank * 16 + t;
            out[((bgA << 6) + step) * 64 + col] = acc.x;
            out[((bgB << 6) + step) * 64 + col] = acc.y;
        }
        __syncthreads();
    }
}

extern "C" void kernel_launch(void* const* d_in, const int* in_sizes, int n_in,
                              void* d_out, int out_size) {
    const float* x      = (const float*)d_in[0];
    const float* Wx     = (const float*)d_in[1];
    const float* Wh     = (const float*)d_in[2];
    const float* b_lstm = (const float*)d_in[3];
    const float* W_head = (const float*)d_in[4];
    const float* b_head = (const float*)d_in[5];
    const float* W_out  = (const float*)d_in[6];
    const float* b_out  = (const float*)d_in[7];
    float* out = (float*)d_out;

    cudaMemcpyToSymbolAsync(g_W, Wx, 128 * 1024 * sizeof(float), 0,
                            cudaMemcpyDeviceToDevice, 0);
    cudaMemcpyToSymbolAsync(g_W, Wh, 256 * 1024 * sizeof(float),
                            128 * 1024 * sizeof(float), cudaMemcpyDeviceToDevice, 0);

    size_t smem = sizeof(SMem);
    cudaFuncSetAttribute(ntm_kernel, cudaFuncAttributeMaxDynamicSharedMemorySize, (int)smem);
    ntm_kernel<<<128, 1024, smem>>>(x, b_lstm, W_head, b_head, W_out, b_out, out);
}

// round 14
// speedup vs baseline: 1.0852x; 1.0852x over previous
#include <cuda_runtime.h>
#include <cooperative_groups.h>
#include <math.h>

namespace cg = cooperative_groups;

#define EPS 1e-8f
typedef unsigned long long u64;
// B=64, S=64, I=64, O=64, N=1024, M=64, H=256, 4H=1024, P=268
// Round 14 = round-8 champion EXACTLY, with one change: the S3 cluster.sync
// (pair-local softmax-sum + boundary-q exchange) is replaced by a pair-local
// DSMEM mbarrier handshake (2 release-arrivals from the writer threads, 
// acquire-cluster parity wait). S1/S45 remain full cluster syncs.

__device__ float g_W[384 * 1024];   // rows 0..127 = Wx, 128..383 = Wh

struct SMem {
    float  mem[64 * 512];     // own batch's memory half, [m][nl] (128 KB)
    float4 part[2048];        // scratch partials (32 KB), region-multiplexed
    float  wr[512], ww[512];  // unnormalized wp mid-step, normalized post-S45
    float  t1[512], t2[512];
    float2 vh[768];           // bank0: [0,64)x [64,128)r [128,384)h ; bank1: +384
    float2 h2c[256];          // current-step full h pairs {hA, hB}
    float2 h2own[64];         // own h quarter pairs
    float  nnp[512];          // per-n norm (own half)
    float  c[2][64];
    float  gates[2][256];
    float  p[272];            // full head output for OWN batch
    float  ppart[4][272];     // head partials from 4 ranks
    float2 krw[64];           // {kr[m], kw[m]}
    float  e[64], a[64];
    float  rrecv[4][64];
    float2 rvec2[64];
    float  scal[16];
    float  qhalo[4];
    float  wh_r[2], wh_w[2];  // normalized prev-w halos
    float  whp_r[2], whp_w[2];// unnormalized boundary wp from peer
    float  xch[4];            // pair softmax-sum slots
    float2 zrecv[4];          // sharpen sums from all 4 ranks
    float2 red[32];
    unsigned long long mbar8; // pair-local S3 barrier
};

__device__ __forceinline__ float sigmoidf_(float x) { return 1.f / (1.f + expf(-x)); }
__device__ __forceinline__ float softplusf_(float x) { return fmaxf(x, 0.f) + log1pf(expf(-fabsf(x))); }

__device__ __forceinline__ u64 pk2(float a, float b) {
    u64 r; asm("mov.b64 %0, {%1, %2};" : "=l"(r) : "f"(a), "f"(b)); return r;
}
__device__ __forceinline__ float2 up2(u64 v) {
    float2 r; asm("mov.b64 {%0, %1}, %2;" : "=f"(r.x), "=f"(r.y) : "l"(v)); return r;
}
__device__ __forceinline__ void fma2(u64& d, u64 a, u64 b) {
    asm("fma.rn.f32x2 %0, %1, %2, %0;" : "+l"(d) : "l"(a), "l"(b));
}
__device__ __forceinline__ u64 fma2n(u64 a, u64 b, u64 c) {
    u64 d; asm("fma.rn.f32x2 %0, %1, %2, %3;" : "=l"(d) : "l"(a), "l"(b), "l"(c)); return d;
}
__device__ __forceinline__ u64 mul2(u64 a, u64 b) {
    u64 d; asm("mul.rn.f32x2 %0, %1, %2;" : "=l"(d) : "l"(a), "l"(b)); return d;
}
__device__ __forceinline__ u64 add2(u64 a, u64 b) {
    u64 d; asm("add.rn.f32x2 %0, %1, %2;" : "=l"(d) : "l"(a), "l"(b)); return d;
}
#define CL_ARRIVE() asm volatile("barrier.cluster.arrive.aligned;" ::: "memory")
#define CL_WAIT()   asm volatile("barrier.cluster.wait.aligned;"   ::: "memory")

__device__ __forceinline__ uint32_t smem_u32(const void* p) {
    uint32_t a;
    asm("{ .reg .u64 t; cvta.to.shared.u64 t, %1; cvt.u32.u64 %0, t; }" : "=r"(a) : "l"(p));
    return a;
}
// Release-arrive (cluster scope) on the SAME-offset mbarrier in target_rank's SMEM.
#define MBAR_ARRIVE_REL(local_mbar, target_rank) \
    asm volatile("{ .reg .b32 ra; mapa.shared::cluster.u32 ra, %0, %1; " \
                 "mbarrier.arrive.release.cluster.shared::cluster.b64 _, [ra]; }" \
                 :: "r"(local_mbar), "r"(target_rank) : "memory")
// Acquire (cluster scope) parity wait on the local mbarrier.
#define MBAR_WAIT_PARITY_CL(mbar, parity) do {                                         \
    uint32_t _done;                                                                    \
    asm volatile("{ .reg .pred p; "                                                    \
        "mbarrier.try_wait.parity.acquire.cluster.shared::cta.b64 p, [%1], %2; "       \
        "selp.b32 %0,1,0,p; }" : "=r"(_done) : "r"(mbar), "r"(parity) : "memory");     \
    while (!_done) {                                                                   \
        asm volatile("{ .reg .pred p; "                                                \
            "mbarrier.try_wait.parity.acquire.cluster.shared::cta.b64 p, [%1], %2, 0x989680; " \
            "selp.b32 %0,1,0,p; }" : "=r"(_done) : "r"(mbar), "r"(parity) : "memory"); \
    }                                                                                  \
} while (0)

// Single-barrier block sum of a float2 across 1024 threads; result in all threads.
__device__ __forceinline__ float2 blockReduceSum2(float2 v, float2* red) {
#pragma unroll
    for (int o = 16; o; o >>= 1) {
        v.x += __shfl_xor_sync(0xffffffffu, v.x, o);
        v.y += __shfl_xor_sync(0xffffffffu, v.y, o);
    }
    if ((threadIdx.x & 31) == 0) red[threadIdx.x >> 5] = v;
    __syncthreads();
    float2 w = red[threadIdx.x & 31];
#pragma unroll
    for (int o = 16; o; o >>= 1) {
        w.x += __shfl_xor_sync(0xffffffffu, w.x, o);
        w.y += __shfl_xor_sync(0xffffffffu, w.y, o);
    }
    return w;
}

__global__ void __launch_bounds__(1024, 1) __cluster_dims__(4, 1, 1)
ntm_kernel(const float* __restrict__ x,       // (64,64,64)
           const float* __restrict__ b_lstm,  // (1024)
           const float* __restrict__ W_head,  // (256,268)
           const float* __restrict__ b_head,  // (268)
           const float* __restrict__ W_out,   // (320,64)
           const float* __restrict__ b_out,   // (64)
           float* __restrict__ out)           // (64,64,64)
{
    extern __shared__ char smraw[];
    SMem* s = (SMem*)smraw;
    cg::cluster_group cl = cg::this_cluster();

    const int rank = (int)cl.block_rank();
    const int clid = blockIdx.x >> 2;
    const int t    = threadIdx.x;

    SMem* P0 = (SMem*)cl.map_shared_rank(smraw, 0);
    SMem* P1 = (SMem*)cl.map_shared_rank(smraw, 1);
    SMem* P2 = (SMem*)cl.map_shared_rank(smraw, 2);
    SMem* P3 = (SMem*)cl.map_shared_rank(smraw, 3);
    SMem* PP[4] = {P0, P1, P2, P3};
    SMem* pp = (SMem*)cl.map_shared_rank(smraw, rank ^ 1);   // pair peer

    float*      partf = (float*)s->part;
    float2*     part2 = (float2*)s->part;
    ulonglong2* partq = (ulonglong2*)s->part;
    float4*     mem4  = (float4*)s->mem;
    ulonglong2* memq  = (ulonglong2*)s->mem;

    const uint32_t mbar = smem_u32(&s->mbar8);
    const int bgA = clid * 2, bgB = clid * 2 + 1;

    // Hoisted out-GEMM constants
    const int jc8 = t & 15, ch8 = t >> 4;
    const int col8 = rank * 16 + jc8;
    float4 w8a;
    {
        int r0 = ch8 * 4;
        w8a = make_float4(W_out[(r0 + 0) * 64 + col8], W_out[(r0 + 1) * 64 + col8],
                          W_out[(r0 + 2) * 64 + col8], W_out[(r0 + 3) * 64 + col8]);
    }
    const float w8b = W_out[(256 + ch8) * 64 + col8];
    const float bo  = (t < 16) ? b_out[rank * 16 + t] : 0.f;

    // ---- init ----
    {
        float4 iv = make_float4(0.01f, 0.01f, 0.01f, 0.01f);
#pragma unroll
        for (int i = 0; i < 8; ++i) mem4[i * 1024 + t] = iv;
        if (t < 512) { float w0 = ((rank & 1) == 0 && t == 0) ? 1.f : 0.f; s->wr[t] = w0; s->ww[t] = w0; }
        if (t < 768) s->vh[t] = make_float2(0.f, 0.f);
        if (t < 256) s->h2c[t] = make_float2(0.f, 0.f);
        if (t < 128) ((float*)s->c)[t] = 0.f;
        if (t < 64)  { s->rvec2[t] = make_float2(0.f, 0.f); s->h2own[t] = make_float2(0.f, 0.f);
                       s->e[t] = 0.f; s->a[t] = 0.f; }   // step-0 deferred update = identity
        if (t < 64) {
            float2 xv = make_float2(x[(bgA << 6) * 64 + t], x[(bgB << 6) * 64 + t]);
            s->vh[t] = xv; s->vh[384 + t] = xv;
        }
        if (t == 0) {
            float hv = (rank & 1) ? 1.f : 0.f;
            s->wh_r[0] = hv; s->wh_w[0] = hv;
            s->wh_r[1] = 0.f; s->wh_w[1] = 0.f;
            asm volatile("mbarrier.init.shared.b64 [%0], %1;" :: "r"(mbar), "r"(2u) : "memory");
        }
    }
    cl.sync();

    float2 xpref = make_float2(0.f, 0.f);

    for (int step = 0; step < 64; ++step) {
        const int prv = step & 1, cur = prv ^ 1;

        // ---- gates GEMM, own 256 cols x 2 batches, packed ----
        {
            int qi = t & 63, qb = qi >> 4, qw = qi & 15;
            int col4 = qb * 64 + rank * 16 + qw;
            int ch = t >> 6;
            const ulonglong2* gw2 = (const ulonglong2*)g_W;
            const float2* vrow = s->vh + prv * 384;
            u64 aA01 = 0ull, aA23 = 0ull, aB01 = 0ull, aB23 = 0ull;
            int r0 = ch * 24;
#pragma unroll 8
            for (int rr = r0; rr < r0 + 24; ++rr) {
                ulonglong2 w2 = gw2[rr * 256 + col4];
                float2 vv = vrow[rr];
                u64 vA2 = pk2(vv.x, vv.x), vB2 = pk2(vv.y, vv.y);
                fma2(aA01, w2.x, vA2); fma2(aA23, w2.y, vA2);
                fma2(aB01, w2.x, vB2); fma2(aB23, w2.y, vB2);
            }
            ulonglong2 sa; sa.x = aA01; sa.y = aA23;
            ulonglong2 sb; sb.x = aB01; sb.y = aB23;
            partq[t] = sa;
            partq[1024 + t] = sb;
        }
        __syncthreads();
        if (t < 128) {
            int bat = t >> 6, qi = t & 63;
            int qb = qi >> 4, qw = qi & 15;
            int col4 = qb * 64 + rank * 16 + qw;
            ulonglong2 bb = ((const ulonglong2*)b_lstm)[col4];
            u64 a01 = bb.x, a23 = bb.y;
#pragma unroll
            for (int ch = 0; ch < 16; ++ch) {
                ulonglong2 pc = partq[bat * 1024 + ch * 64 + qi];
                a01 = add2(a01, pc.x); a23 = add2(a23, pc.y);
            }
            ulonglong2 g; g.x = a01; g.y = a23;
            ((ulonglong2*)s->gates[bat])[qi] = g;
        }
        __syncthreads();

        // ---- LSTM pointwise on own quarter; broadcast h; stash own pairs ----
        if (t < 128) {
            int bat = t >> 6, jl = t & 63;
            float ig = s->gates[bat][jl],       fg = s->gates[bat][64 + jl],
                  gg = s->gates[bat][128 + jl], og = s->gates[bat][192 + jl];
            float cc = sigmoidf_(fg) * s->c[bat][jl] + sigmoidf_(ig) * tanhf(gg);
            s->c[bat][jl] = cc;
            float hv = sigmoidf_(og) * tanhf(cc);
            int gj = rank * 64 + jl;
            ((float*)&s->h2own[jl])[bat] = hv;
#pragma unroll
            for (int i = 0; i < 4; ++i) {
                ((float*)&PP[i]->vh[128 + cur * 384 + gj])[bat] = hv;
                ((float*)&PP[i]->h2c[gj])[bat] = hv;
            }
        }
        __syncthreads();

        // ---- head PARTIAL GEMM from own h quarter (64 rows x 268 cols, packed) ----
        if (t < 536) {
            int half = t / 268, j = t - half * 268;
            const float* whp = W_head + (64 * rank + half * 32) * 268 + j;
            u64 acc = 0ull;
#pragma unroll 8
            for (int k = 0; k < 32; ++k) {
                float w = whp[k * 268];
                u64 hv = *(const u64*)(s->h2own + half * 32 + k);
                fma2(acc, hv, pk2(w, w));
            }
            part2[t] = up2(acc);
        }
        __syncthreads();
        if (t < 268) {
            float2 pa = part2[t], pb = part2[t + 268];
            float vx = pa.x + pb.x, vy = pa.y + pb.y;
            P0->ppart[rank][t] = vx; P1->ppart[rank][t] = vx;
            P2->ppart[rank][t] = vy; P3->ppart[rank][t] = vy;
        }
        CL_ARRIVE();   // S1 arrive
        // ---- S1 shadow: DEFERRED memory update (prev ww,e,a) + norm accumulation ----
        {
            int n4 = t & 127, mch = t >> 7;
            ulonglong2 ww2 = ((const ulonglong2*)s->ww)[n4];
            const u64 one2 = pk2(1.f, 1.f);
            u64 nn01 = 0ull, nn23 = 0ull;
#pragma unroll 4
            for (int mi = 0; mi < 8; ++mi) {
                int m = mch * 8 + mi;
                float em = s->e[m], am = s->a[m];
                u64 nem2 = pk2(-em, -em), am2 = pk2(am, am);
                ulonglong2 v2 = memq[m * 128 + n4];
                v2.x = fma2n(v2.x, fma2n(ww2.x, nem2, one2), mul2(ww2.x, am2));
                v2.y = fma2n(v2.y, fma2n(ww2.y, nem2, one2), mul2(ww2.y, am2));
                memq[m * 128 + n4] = v2;
                fma2(nn01, v2.x, v2.x); fma2(nn23, v2.y, v2.y);
            }
            ulonglong2 nnq; nnq.x = nn01; nnq.y = nn23;
            ((ulonglong2*)s->part)[1024 + mch * 128 + n4] = nnq;
        }
        CL_WAIT();     // S1: full h + head partials everywhere
        __syncthreads();   // order shadow writes intra-CTA

        // ---- post-S1: sum head partials (own batch) + reduce norms ----
        if (t < 268) {
            s->p[t] = s->ppart[0][t] + s->ppart[1][t] + s->ppart[2][t] + s->ppart[3][t]
                    + b_head[t];
        } else if (t >= 512) {
            int nl0 = t - 512;
            float nn = 0.f;
#pragma unroll
            for (int mch = 0; mch < 8; ++mch) nn += partf[4096 + mch * 512 + nl0];
            s->nnp[nl0] = nn;
        }
        __syncthreads();

        // ---- parse heads ----
        if (t < 64) s->krw[t].x = tanhf(s->p[t]);
        else if (t < 128) s->krw[t - 64].y = tanhf(s->p[70 + t - 64]);
        else if (t < 192) s->e[t - 128] = sigmoidf_(s->p[140 + (t - 128)]);
        else if (t < 256) s->a[t - 192] = s->p[204 + (t - 192)];
        else if (t == 256) {
            s->scal[0] = softplusf_(s->p[64]);
            s->scal[1] = sigmoidf_(s->p[65]);
            float a0 = s->p[66], a1 = s->p[67], a2 = s->p[68];
            float mx = fmaxf(a0, fmaxf(a1, a2));
            float e0 = expf(a0 - mx), e1 = expf(a1 - mx), e2 = expf(a2 - mx);
            float sm = e0 + e1 + e2;
            s->scal[2] = e0 / sm; s->scal[3] = e1 / sm; s->scal[4] = e2 / sm;
            s->scal[5] = 1.f + softplusf_(s->p[69]);
        } else if (t == 288) {
            s->scal[8] = softplusf_(s->p[134]);
            s->scal[9] = sigmoidf_(s->p[135]);
            float a0 = s->p[136], a1 = s->p[137], a2 = s->p[138];
            float mx = fmaxf(a0, fmaxf(a1, a2));
            float e0 = expf(a0 - mx), e1 = expf(a1 - mx), e2 = expf(a2 - mx);
            float sm = e0 + e1 + e2;
            s->scal[10] = e0 / sm; s->scal[11] = e1 / sm; s->scal[12] = e2 / sm;
            s->scal[13] = 1.f + softplusf_(s->p[139]);
        }
        __syncthreads();
        if (t < 32) {
            float kv = s->krw[t].x, kv2 = s->krw[t + 32].x;
            float v = kv * kv + kv2 * kv2;
#pragma unroll
            for (int o = 16; o; o >>= 1) v += __shfl_xor_sync(0xffffffffu, v, o);
            if (t == 0) s->scal[6] = sqrtf(v);
        } else if (t < 64) {
            int l = t - 32;
            float kv = s->krw[l].y, kv2 = s->krw[l + 32].y;
            float v = kv * kv + kv2 * kv2;
#pragma unroll
            for (int o = 16; o; o >>= 1) v += __shfl_xor_sync(0xffffffffu, v, o);
            if (l == 0) s->scal[7] = sqrtf(v);
        }
        __syncthreads();

        // ---- addressing dots over own 512 n-rows (updated mem), packed ----
        const int nl = t & 511, mh = t >> 9;
        {
            u64 drw = 0ull;
            int m0 = mh * 32;
#pragma unroll 8
            for (int m = m0; m < m0 + 32; ++m) {
                float v = s->mem[m * 512 + nl];
                u64 kv = *(const u64*)(s->krw + m);
                fma2(drw, kv, pk2(v, v));
            }
            float2 d = up2(drw);
            s->part[t] = make_float4(d.x, d.y, 0.f, 0.f);
        }
        __syncthreads();
        const bool lead = (t < 512);
        float qr = 0.f, qw = 0.f, er = 0.f, ew = 0.f;
        if (lead) {
            float4 p0 = s->part[t], p1 = s->part[t + 512];
            float dr = p0.x + p1.x, dw = p0.y + p1.y;
            float nrm = sqrtf(s->nnp[nl]);
            qr = s->scal[0] * (dr / (s->scal[6] * nrm + EPS));
            qw = s->scal[8] * (dw / (s->scal[7] * nrm + EPS));
            if (nl == 0)   { pp->qhalo[0] = qr; pp->qhalo[2] = qw; }
            if (nl == 511) { pp->qhalo[1] = qr; pp->qhalo[3] = qw; }
            er = expf(qr);
            ew = expf(qw);
        }
        float2 lsum = blockReduceSum2(make_float2(er, ew), s->red);
        if (t == 0) { pp->xch[0] = lsum.x; pp->xch[1] = lsum.y; }
        // ---- S3 replacement: pair-local mbarrier handshake ----
        if (t == 0 || t == 511) MBAR_ARRIVE_REL(mbar, rank ^ 1);
        // ---- S3 shadow: out-GEMM h-part ----
        {
            const float* hb = (const float*)s->h2c;
            int r0 = ch8 * 4;
            u64 acc = 0ull;
            u64 h0 = *(const u64*)(hb + 2 * (r0 + 0));
            u64 h1 = *(const u64*)(hb + 2 * (r0 + 1));
            u64 h2 = *(const u64*)(hb + 2 * (r0 + 2));
            u64 h3 = *(const u64*)(hb + 2 * (r0 + 3));
            fma2(acc, h0, pk2(w8a.x, w8a.x));
            fma2(acc, h1, pk2(w8a.y, w8a.y));
            fma2(acc, h2, pk2(w8a.z, w8a.z));
            fma2(acc, h3, pk2(w8a.w, w8a.w));
            part2[3072 + t] = up2(acc);
        }
        MBAR_WAIT_PARITY_CL(mbar, step & 1);   // S3: pair sums + boundary q visible
        const float gsr = lsum.x + s->xch[0];
        const float gsw = lsum.y + s->xch[1];
        const float g_r = s->scal[1], g_w = s->scal[9];
        if (lead) {
            float wgr = g_r * (er / gsr) + (1.f - g_r) * s->wr[nl];
            float wgw = g_w * (ew / gsw) + (1.f - g_w) * s->ww[nl];
            s->t1[nl] = wgr;
            s->t2[nl] = wgw;
        }
        __syncthreads();
        float wpr = 0.f, wpw = 0.f;
        if (lead) {
            float t1p = (nl == 511) ? (g_r * (expf(s->qhalo[0]) / gsr) + (1.f - g_r) * s->wh_r[0]) : s->t1[nl + 1];
            float t1m = (nl == 0)   ? (g_r * (expf(s->qhalo[1]) / gsr) + (1.f - g_r) * s->wh_r[1]) : s->t1[nl - 1];
            float t2p = (nl == 511) ? (g_w * (expf(s->qhalo[2]) / gsw) + (1.f - g_w) * s->wh_w[0]) : s->t2[nl + 1];
            float t2m = (nl == 0)   ? (g_w * (expf(s->qhalo[3]) / gsw) + (1.f - g_w) * s->wh_w[1]) : s->t2[nl - 1];
            float wsr = s->scal[2]  * t1p + s->scal[3]  * s->t1[nl] + s->scal[4]  * t1m;
            float wsw = s->scal[10] * t2p + s->scal[11] * s->t2[nl] + s->scal[12] * t2m;
            wpr = (wsr > 0.f) ? expf(s->scal[5]  * logf(wsr)) : 0.f;
            wpw = (wsw > 0.f) ? expf(s->scal[13] * logf(wsw)) : 0.f;
            s->wr[nl] = wpr;      // UNNORMALIZED until post-S45
            s->ww[nl] = wpw;
            if (nl == 0)   { pp->whp_r[0] = wpr; pp->whp_w[0] = wpw; }
            if (nl == 511) { pp->whp_r[1] = wpr; pp->whp_w[1] = wpw; }
        }
        float2 lsp = blockReduceSum2(make_float2(wpr, wpw), s->red);  // bar publishes s->wr

        // ---- read pass with UNNORMALIZED wr ----
        {
            int n4 = t & 127, mch = t >> 7, wid = t >> 5;
            ulonglong2 wr2 = ((const ulonglong2*)s->wr)[n4];
#pragma unroll 4
            for (int mi = 0; mi < 8; ++mi) {
                int m = mch * 8 + mi;
                ulonglong2 v2 = memq[m * 128 + n4];
                u64 rp2 = 0ull;
                fma2(rp2, wr2.x, v2.x); fma2(rp2, wr2.y, v2.y);
                float2 rr = up2(rp2);
                float rp = rr.x + rr.y;
#pragma unroll
                for (int o = 16; o; o >>= 1) rp += __shfl_xor_sync(0xffffffffu, rp, o);
                if ((t & 31) == 0) partf[2048 + wid * 8 + mi] = rp;
            }
        }
        __syncthreads();
        if (t < 64) {
            int grp = t >> 3, mi = t & 7;
            float v = partf[2048 + (grp * 4 + 0) * 8 + mi]
                    + partf[2048 + (grp * 4 + 1) * 8 + mi]
                    + partf[2048 + (grp * 4 + 2) * 8 + mi]
                    + partf[2048 + (grp * 4 + 3) * 8 + mi];
#pragma unroll
            for (int i = 0; i < 4; ++i) PP[i]->rrecv[rank][t] = v;
        }
        if (t == 0) {
#pragma unroll
            for (int i = 0; i < 4; ++i) PP[i]->zrecv[rank] = lsp;
        }
        CL_ARRIVE();   // S45 arrive
        if (t < 64) {
            int sn = (step < 63) ? step + 1 : 63;
            xpref = make_float2(x[((bgA << 6) + sn) * 64 + t],
                                x[((bgB << 6) + sn) * 64 + t]);
        }
        CL_WAIT();     // S45: sharpen sums + r partials + boundary wp

        // ---- post-S45: normalize, assemble r, stage next inputs ----
        {
            float2 z0 = s->zrecv[0], z1 = s->zrecv[1], z2 = s->zrecv[2], z3 = s->zrecv[3];
            float invZrA = 1.f / ((z0.x + z1.x) + EPS), invZwA = 1.f / ((z0.y + z1.y) + EPS);
            float invZrB = 1.f / ((z2.x + z3.x) + EPS), invZwB = 1.f / ((z2.y + z3.y) + EPS);
            float invZr = (rank < 2) ? invZrA : invZrB;
            float invZw = (rank < 2) ? invZwA : invZwB;
            if (lead) { s->wr[nl] *= invZr; s->ww[nl] *= invZw; }
            if (t == 0) {
                s->wh_r[0] = s->whp_r[0] * invZr; s->wh_r[1] = s->whp_r[1] * invZr;
                s->wh_w[0] = s->whp_w[0] * invZw; s->wh_w[1] = s->whp_w[1] * invZw;
            }
            if (t < 64) {
                float2 rv = make_float2((s->rrecv[0][t] + s->rrecv[1][t]) * invZrA,
                                        (s->rrecv[2][t] + s->rrecv[3][t]) * invZrB);
                s->rvec2[t] = rv;
                s->vh[64 + t] = rv;   s->vh[448 + t] = rv;
                s->vh[t] = xpref;     s->vh[384 + t] = xpref;
            }
        }
        __syncthreads();

        // ---- out: add r-part, reduce, write ----
        {
            float2 rv = s->rvec2[ch8];
            float2 pv = part2[3072 + t];
            pv.x += rv.x * w8b; pv.y += rv.y * w8b;
            part2[3072 + t] = pv;
        }
        __syncthreads();
        if (t < 128) {
            int jc = t & 15, g = t >> 4;
            float2 acc = make_float2(0.f, 0.f);
#pragma unroll
            for (int k = 0; k < 8; ++k) {
                float2 pv = part2[3072 + (g * 8 + k) * 16 + jc];
                acc.x += pv.x; acc.y += pv.y;
            }
            part2[t] = acc;
        }
        __syncthreads();
        if (t < 16) {
            float2 acc = make_float2(bo, bo);
#pragma unroll
            for (int g = 0; g < 8; ++g) {
                float2 pv = part2[g * 16 + t];
                acc.x += pv.x; acc.y += pv.y;
            }
            int col = rank * 16 + t;
            out[((bgA << 6) + step) * 64 + col] = acc.x;
            out[((bgB << 6) + step) * 64 + col] = acc.y;
        }
        __syncthreads();
    }
}

extern "C" void kernel_launch(void* const* d_in, const int* in_sizes, int n_in,
                              void* d_out, int out_size) {
    const float* x      = (const float*)d_in[0];
    const float* Wx     = (const float*)d_in[1];
    const float* Wh     = (const float*)d_in[2];
    const float* b_lstm = (const float*)d_in[3];
    const float* W_head = (const float*)d_in[4];
    const float* b_head = (const float*)d_in[5];
    const float* W_out  = (const float*)d_in[6];
    const float* b_out  = (const float*)d_in[7];
    float* out = (float*)d_out;

    cudaMemcpyToSymbolAsync(g_W, Wx, 128 * 1024 * sizeof(float), 0,
                            cudaMemcpyDeviceToDevice, 0);
    cudaMemcpyToSymbolAsync(g_W, Wh, 256 * 1024 * sizeof(float),
                            128 * 1024 * sizeof(float), cudaMemcpyDeviceToDevice, 0);

    size_t smem = sizeof(SMem);
    cudaFuncSetAttribute(ntm_kernel, cudaFuncAttributeMaxDynamicSharedMemorySize, (int)smem);
    ntm_kernel<<<128, 1024, smem>>>(x, b_lstm, W_head, b_head, W_out, b_out, out);
}

// round 15
// speedup vs baseline: 1.2628x; 1.1636x over previous
#include <cuda_runtime.h>
#include <cooperative_groups.h>
#include <math.h>

namespace cg = cooperative_groups;

#define EPS 1e-8f
typedef unsigned long long u64;
// B=64, S=64, I=64, O=64, N=1024, M=64, H=256, 4H=1024, P=268
// Round 15 = round-8 champion + 3 critical-path trims:
//  (1) key norms folded into parse phase (warps 10-11, recompute tanh from p)
//  (2) er/ew stored to t1/t2 pre-S3; wg computed inline in sharpen (no wg phase);
//      sharpen outputs to wpa/wpb (read pass + post-S45 normalize read those)
//  (3) sharpen-sum second reduce stage deferred past the read pass (warp 2)

__device__ float g_W[384 * 1024];   // rows 0..127 = Wx, 128..383 = Wh

struct SMem {
    float  mem[64 * 512];     // own batch's memory half, [m][nl] (128 KB)
    float4 part[2048];        // scratch partials (32 KB), region-multiplexed
    float  wr[512], ww[512];  // NORMALIZED w from prev step (read-only mid-step)
    float  t1[512], t2[512];  // er / ew this step
    float  wpa[512], wpb[512];// unnormalized sharpened wp (this step)
    float2 vh[768];           // bank0: [0,64)x [64,128)r [128,384)h ; bank1: +384
    float2 h2c[256];          // current-step full h pairs {hA, hB}
    float2 h2own[64];         // own h quarter pairs
    float  nnp[512];          // per-n norm (own half)
    float  c[2][64];
    float  gates[2][256];
    float  p[272];            // full head output for OWN batch
    float  ppart[4][272];     // head partials from 4 ranks
    float2 krw[64];           // {kr[m], kw[m]}
    float  e[64], a[64];
    float  rrecv[4][64];
    float2 rvec2[64];
    float  scal[16];
    float  qhalo[4];
    float  wh_r[2], wh_w[2];  // normalized prev-w halos
    float  whp_r[2], whp_w[2];// unnormalized boundary wp from peer
    float  xch[4];            // pair softmax-sum slots
    float2 zrecv[4];          // sharpen sums from all 4 ranks
    float2 red[32];
};

__device__ __forceinline__ float sigmoidf_(float x) { return 1.f / (1.f + expf(-x)); }
__device__ __forceinline__ float softplusf_(float x) { return fmaxf(x, 0.f) + log1pf(expf(-fabsf(x))); }

__device__ __forceinline__ u64 pk2(float a, float b) {
    u64 r; asm("mov.b64 %0, {%1, %2};" : "=l"(r) : "f"(a), "f"(b)); return r;
}
__device__ __forceinline__ float2 up2(u64 v) {
    float2 r; asm("mov.b64 {%0, %1}, %2;" : "=f"(r.x), "=f"(r.y) : "l"(v)); return r;
}
__device__ __forceinline__ void fma2(u64& d, u64 a, u64 b) {
    asm("fma.rn.f32x2 %0, %1, %2, %0;" : "+l"(d) : "l"(a), "l"(b));
}
__device__ __forceinline__ u64 fma2n(u64 a, u64 b, u64 c) {
    u64 d; asm("fma.rn.f32x2 %0, %1, %2, %3;" : "=l"(d) : "l"(a), "l"(b), "l"(c)); return d;
}
__device__ __forceinline__ u64 mul2(u64 a, u64 b) {
    u64 d; asm("mul.rn.f32x2 %0, %1, %2;" : "=l"(d) : "l"(a), "l"(b)); return d;
}
__device__ __forceinline__ u64 add2(u64 a, u64 b) {
    u64 d; asm("add.rn.f32x2 %0, %1, %2;" : "=l"(d) : "l"(a), "l"(b)); return d;
}
#define CL_ARRIVE() asm volatile("barrier.cluster.arrive.aligned;" ::: "memory")
#define CL_WAIT()   asm volatile("barrier.cluster.wait.aligned;"   ::: "memory")

// Single-barrier block sum of a float2 across 1024 threads; result in all threads.
__device__ __forceinline__ float2 blockReduceSum2(float2 v, float2* red) {
#pragma unroll
    for (int o = 16; o; o >>= 1) {
        v.x += __shfl_xor_sync(0xffffffffu, v.x, o);
        v.y += __shfl_xor_sync(0xffffffffu, v.y, o);
    }
    if ((threadIdx.x & 31) == 0) red[threadIdx.x >> 5] = v;
    __syncthreads();
    float2 w = red[threadIdx.x & 31];
#pragma unroll
    for (int o = 16; o; o >>= 1) {
        w.x += __shfl_xor_sync(0xffffffffu, w.x, o);
        w.y += __shfl_xor_sync(0xffffffffu, w.y, o);
    }
    return w;
}

__global__ void __launch_bounds__(1024, 1) __cluster_dims__(4, 1, 1)
ntm_kernel(const float* __restrict__ x,       // (64,64,64)
           const float* __restrict__ b_lstm,  // (1024)
           const float* __restrict__ W_head,  // (256,268)
           const float* __restrict__ b_head,  // (268)
           const float* __restrict__ W_out,   // (320,64)
           const float* __restrict__ b_out,   // (64)
           float* __restrict__ out)           // (64,64,64)
{
    extern __shared__ char smraw[];
    SMem* s = (SMem*)smraw;
    cg::cluster_group cl = cg::this_cluster();

    const int rank = (int)cl.block_rank();
    const int clid = blockIdx.x >> 2;
    const int t    = threadIdx.x;

    SMem* P0 = (SMem*)cl.map_shared_rank(smraw, 0);
    SMem* P1 = (SMem*)cl.map_shared_rank(smraw, 1);
    SMem* P2 = (SMem*)cl.map_shared_rank(smraw, 2);
    SMem* P3 = (SMem*)cl.map_shared_rank(smraw, 3);
    SMem* PP[4] = {P0, P1, P2, P3};
    SMem* pp = (SMem*)cl.map_shared_rank(smraw, rank ^ 1);   // pair peer

    float*      partf = (float*)s->part;
    float2*     part2 = (float2*)s->part;
    ulonglong2* partq = (ulonglong2*)s->part;
    float4*     mem4  = (float4*)s->mem;
    ulonglong2* memq  = (ulonglong2*)s->mem;

    const int bgA = clid * 2, bgB = clid * 2 + 1;

    // Hoisted out-GEMM constants
    const int jc8 = t & 15, ch8 = t >> 4;
    const int col8 = rank * 16 + jc8;
    float4 w8a;
    {
        int r0 = ch8 * 4;
        w8a = make_float4(W_out[(r0 + 0) * 64 + col8], W_out[(r0 + 1) * 64 + col8],
                          W_out[(r0 + 2) * 64 + col8], W_out[(r0 + 3) * 64 + col8]);
    }
    const float w8b = W_out[(256 + ch8) * 64 + col8];
    const float bo  = (t < 16) ? b_out[rank * 16 + t] : 0.f;

    // ---- init ----
    {
        float4 iv = make_float4(0.01f, 0.01f, 0.01f, 0.01f);
#pragma unroll
        for (int i = 0; i < 8; ++i) mem4[i * 1024 + t] = iv;
        if (t < 512) { float w0 = ((rank & 1) == 0 && t == 0) ? 1.f : 0.f; s->wr[t] = w0; s->ww[t] = w0; }
        if (t < 768) s->vh[t] = make_float2(0.f, 0.f);
        if (t < 256) s->h2c[t] = make_float2(0.f, 0.f);
        if (t < 128) ((float*)s->c)[t] = 0.f;
        if (t < 64)  { s->rvec2[t] = make_float2(0.f, 0.f); s->h2own[t] = make_float2(0.f, 0.f);
                       s->e[t] = 0.f; s->a[t] = 0.f; }   // step-0 deferred update = identity
        if (t < 64) {
            float2 xv = make_float2(x[(bgA << 6) * 64 + t], x[(bgB << 6) * 64 + t]);
            s->vh[t] = xv; s->vh[384 + t] = xv;
        }
        if (t == 0) {
            float hv = (rank & 1) ? 1.f : 0.f;
            s->wh_r[0] = hv; s->wh_w[0] = hv;
            s->wh_r[1] = 0.f; s->wh_w[1] = 0.f;
        }
    }
    cl.sync();

    float2 xpref = make_float2(0.f, 0.f);

    for (int step = 0; step < 64; ++step) {
        const int prv = step & 1, cur = prv ^ 1;

        // ---- gates GEMM, own 256 cols x 2 batches, packed ----
        {
            int qi = t & 63, qb = qi >> 4, qw = qi & 15;
            int col4 = qb * 64 + rank * 16 + qw;
            int ch = t >> 6;
            const ulonglong2* gw2 = (const ulonglong2*)g_W;
            const float2* vrow = s->vh + prv * 384;
            u64 aA01 = 0ull, aA23 = 0ull, aB01 = 0ull, aB23 = 0ull;
            int r0 = ch * 24;
#pragma unroll 8
            for (int rr = r0; rr < r0 + 24; ++rr) {
                ulonglong2 w2 = gw2[rr * 256 + col4];
                float2 vv = vrow[rr];
                u64 vA2 = pk2(vv.x, vv.x), vB2 = pk2(vv.y, vv.y);
                fma2(aA01, w2.x, vA2); fma2(aA23, w2.y, vA2);
                fma2(aB01, w2.x, vB2); fma2(aB23, w2.y, vB2);
            }
            ulonglong2 sa; sa.x = aA01; sa.y = aA23;
            ulonglong2 sb; sb.x = aB01; sb.y = aB23;
            partq[t] = sa;
            partq[1024 + t] = sb;
        }
        __syncthreads();
        if (t < 128) {
            int bat = t >> 6, qi = t & 63;
            int qb = qi >> 4, qw = qi & 15;
            int col4 = qb * 64 + rank * 16 + qw;
            ulonglong2 bb = ((const ulonglong2*)b_lstm)[col4];
            u64 a01 = bb.x, a23 = bb.y;
#pragma unroll
            for (int ch = 0; ch < 16; ++ch) {
                ulonglong2 pc = partq[bat * 1024 + ch * 64 + qi];
                a01 = add2(a01, pc.x); a23 = add2(a23, pc.y);
            }
            ulonglong2 g; g.x = a01; g.y = a23;
            ((ulonglong2*)s->gates[bat])[qi] = g;
        }
        __syncthreads();

        // ---- LSTM pointwise on own quarter; broadcast h; stash own pairs ----
        if (t < 128) {
            int bat = t >> 6, jl = t & 63;
            float ig = s->gates[bat][jl],       fg = s->gates[bat][64 + jl],
                  gg = s->gates[bat][128 + jl], og = s->gates[bat][192 + jl];
            float cc = sigmoidf_(fg) * s->c[bat][jl] + sigmoidf_(ig) * tanhf(gg);
            s->c[bat][jl] = cc;
            float hv = sigmoidf_(og) * tanhf(cc);
            int gj = rank * 64 + jl;
            ((float*)&s->h2own[jl])[bat] = hv;
#pragma unroll
            for (int i = 0; i < 4; ++i) {
                ((float*)&PP[i]->vh[128 + cur * 384 + gj])[bat] = hv;
                ((float*)&PP[i]->h2c[gj])[bat] = hv;
            }
        }
        __syncthreads();

        // ---- head PARTIAL GEMM from own h quarter (64 rows x 268 cols, packed) ----
        if (t < 536) {
            int half = t / 268, j = t - half * 268;
            const float* whp = W_head + (64 * rank + half * 32) * 268 + j;
            u64 acc = 0ull;
#pragma unroll 8
            for (int k = 0; k < 32; ++k) {
                float w = whp[k * 268];
                u64 hv = *(const u64*)(s->h2own + half * 32 + k);
                fma2(acc, hv, pk2(w, w));
            }
            part2[t] = up2(acc);
        }
        __syncthreads();
        if (t < 268) {
            float2 pa = part2[t], pb = part2[t + 268];
            float vx = pa.x + pb.x, vy = pa.y + pb.y;
            P0->ppart[rank][t] = vx; P1->ppart[rank][t] = vx;
            P2->ppart[rank][t] = vy; P3->ppart[rank][t] = vy;
        }
        CL_ARRIVE();   // S1 arrive
        // ---- S1 shadow: DEFERRED memory update (prev ww,e,a) + norm accumulation ----
        {
            int n4 = t & 127, mch = t >> 7;
            ulonglong2 ww2 = ((const ulonglong2*)s->ww)[n4];
            const u64 one2 = pk2(1.f, 1.f);
            u64 nn01 = 0ull, nn23 = 0ull;
#pragma unroll 4
            for (int mi = 0; mi < 8; ++mi) {
                int m = mch * 8 + mi;
                float em = s->e[m], am = s->a[m];
                u64 nem2 = pk2(-em, -em), am2 = pk2(am, am);
                ulonglong2 v2 = memq[m * 128 + n4];
                v2.x = fma2n(v2.x, fma2n(ww2.x, nem2, one2), mul2(ww2.x, am2));
                v2.y = fma2n(v2.y, fma2n(ww2.y, nem2, one2), mul2(ww2.y, am2));
                memq[m * 128 + n4] = v2;
                fma2(nn01, v2.x, v2.x); fma2(nn23, v2.y, v2.y);
            }
            ulonglong2 nnq; nnq.x = nn01; nnq.y = nn23;
            ((ulonglong2*)s->part)[1024 + mch * 128 + n4] = nnq;
        }
        CL_WAIT();     // S1: full h + head partials everywhere
        __syncthreads();   // order shadow writes intra-CTA

        // ---- post-S1: sum head partials (own batch) + reduce norms ----
        if (t < 268) {
            s->p[t] = s->ppart[0][t] + s->ppart[1][t] + s->ppart[2][t] + s->ppart[3][t]
                    + b_head[t];
        } else if (t >= 512) {
            int nl0 = t - 512;
            float nn = 0.f;
#pragma unroll
            for (int mch = 0; mch < 8; ++mch) nn += partf[4096 + mch * 512 + nl0];
            s->nnp[nl0] = nn;
        }
        __syncthreads();

        // ---- parse heads + key norms (folded into one phase) ----
        if (t < 64) s->krw[t].x = tanhf(s->p[t]);
        else if (t < 128) s->krw[t - 64].y = tanhf(s->p[70 + t - 64]);
        else if (t < 192) s->e[t - 128] = sigmoidf_(s->p[140 + (t - 128)]);
        else if (t < 256) s->a[t - 192] = s->p[204 + (t - 192)];
        else if (t == 256) {
            s->scal[0] = softplusf_(s->p[64]);
            s->scal[1] = sigmoidf_(s->p[65]);
            float a0 = s->p[66], a1 = s->p[67], a2 = s->p[68];
            float mx = fmaxf(a0, fmaxf(a1, a2));
            float e0 = expf(a0 - mx), e1 = expf(a1 - mx), e2 = expf(a2 - mx);
            float sm = e0 + e1 + e2;
            s->scal[2] = e0 / sm; s->scal[3] = e1 / sm; s->scal[4] = e2 / sm;
            s->scal[5] = 1.f + softplusf_(s->p[69]);
        } else if (t == 288) {
            s->scal[8] = softplusf_(s->p[134]);
            s->scal[9] = sigmoidf_(s->p[135]);
            float a0 = s->p[136], a1 = s->p[137], a2 = s->p[138];
            float mx = fmaxf(a0, fmaxf(a1, a2));
            float e0 = expf(a0 - mx), e1 = expf(a1 - mx), e2 = expf(a2 - mx);
            float sm = e0 + e1 + e2;
            s->scal[10] = e0 / sm; s->scal[11] = e1 / sm; s->scal[12] = e2 / sm;
            s->scal[13] = 1.f + softplusf_(s->p[139]);
        } else if (t >= 320 && t < 352) {
            int l = t - 320;
            float k0 = tanhf(s->p[l]), k1 = tanhf(s->p[l + 32]);
            float v = k0 * k0 + k1 * k1;
#pragma unroll
            for (int o = 16; o; o >>= 1) v += __shfl_xor_sync(0xffffffffu, v, o);
            if (l == 0) s->scal[6] = sqrtf(v);
        } else if (t >= 352 && t < 384) {
            int l = t - 352;
            float k0 = tanhf(s->p[70 + l]), k1 = tanhf(s->p[70 + l + 32]);
            float v = k0 * k0 + k1 * k1;
#pragma unroll
            for (int o = 16; o; o >>= 1) v += __shfl_xor_sync(0xffffffffu, v, o);
            if (l == 0) s->scal[7] = sqrtf(v);
        }
        __syncthreads();

        // ---- addressing dots over own 512 n-rows (updated mem), packed ----
        const int nl = t & 511, mh = t >> 9;
        {
            u64 drw = 0ull;
            int m0 = mh * 32;
#pragma unroll 8
            for (int m = m0; m < m0 + 32; ++m) {
                float v = s->mem[m * 512 + nl];
                u64 kv = *(const u64*)(s->krw + m);
                fma2(drw, kv, pk2(v, v));
            }
            float2 d = up2(drw);
            s->part[t] = make_float4(d.x, d.y, 0.f, 0.f);
        }
        __syncthreads();
        const bool lead = (t < 512);
        float qr = 0.f, qw = 0.f, er = 0.f, ew = 0.f;
        if (lead) {
            float4 p0 = s->part[t], p1 = s->part[t + 512];
            float dr = p0.x + p1.x, dw = p0.y + p1.y;
            float nrm = sqrtf(s->nnp[nl]);
            qr = s->scal[0] * (dr / (s->scal[6] * nrm + EPS));
            qw = s->scal[8] * (dw / (s->scal[7] * nrm + EPS));
            if (nl == 0)   { pp->qhalo[0] = qr; pp->qhalo[2] = qw; }
            if (nl == 511) { pp->qhalo[1] = qr; pp->qhalo[3] = qw; }
            er = expf(qr);
            ew = expf(qw);
            s->t1[nl] = er;     // er/ew staged pre-S3 (replaces the wg phase)
            s->t2[nl] = ew;
        }
        float2 lsum = blockReduceSum2(make_float2(er, ew), s->red);  // bar publishes t1/t2
        if (t == 0) { pp->xch[0] = lsum.x; pp->xch[1] = lsum.y; }
        CL_ARRIVE();   // S3 arrive
        // ---- S3 shadow: out-GEMM h-part ----
        {
            const float* hb = (const float*)s->h2c;
            int r0 = ch8 * 4;
            u64 acc = 0ull;
            u64 h0 = *(const u64*)(hb + 2 * (r0 + 0));
            u64 h1 = *(const u64*)(hb + 2 * (r0 + 1));
            u64 h2 = *(const u64*)(hb + 2 * (r0 + 2));
            u64 h3 = *(const u64*)(hb + 2 * (r0 + 3));
            fma2(acc, h0, pk2(w8a.x, w8a.x));
            fma2(acc, h1, pk2(w8a.y, w8a.y));
            fma2(acc, h2, pk2(w8a.z, w8a.z));
            fma2(acc, h3, pk2(w8a.w, w8a.w));
            part2[3072 + t] = up2(acc);
        }
        CL_WAIT();     // S3: pair softmax sums + boundary q
        const float gsr = lsum.x + s->xch[0];
        const float gsw = lsum.y + s->xch[1];
        const float g_r = s->scal[1], g_w = s->scal[9];
        const float igr = 1.f / gsr, igw = 1.f / gsw;
        float wpr = 0.f, wpw = 0.f;
        if (lead) {
            // inline wg for nl-1, nl, nl+1 (er from t1/t2, prev-w from wr/ww; both
            // read-only this phase — outputs go to wpa/wpb)
            float wgc_r = g_r * (er * igr) + (1.f - g_r) * s->wr[nl];
            float wgc_w = g_w * (ew * igw) + (1.f - g_w) * s->ww[nl];
            float erp = (nl == 511) ? expf(s->qhalo[0]) : s->t1[nl + 1];
            float ewp = (nl == 511) ? expf(s->qhalo[2]) : s->t2[nl + 1];
            float wrp = (nl == 511) ? s->wh_r[0] : s->wr[nl + 1];
            float wwp = (nl == 511) ? s->wh_w[0] : s->ww[nl + 1];
            float wgp_r = g_r * (erp * igr) + (1.f - g_r) * wrp;
            float wgp_w = g_w * (ewp * igw) + (1.f - g_w) * wwp;
            float erm = (nl == 0) ? expf(s->qhalo[1]) : s->t1[nl - 1];
            float ewm = (nl == 0) ? expf(s->qhalo[3]) : s->t2[nl - 1];
            float wrm = (nl == 0) ? s->wh_r[1] : s->wr[nl - 1];
            float wwm = (nl == 0) ? s->wh_w[1] : s->ww[nl - 1];
            float wgm_r = g_r * (erm * igr) + (1.f - g_r) * wrm;
            float wgm_w = g_w * (ewm * igw) + (1.f - g_w) * wwm;
            float wsr = s->scal[2]  * wgp_r + s->scal[3]  * wgc_r + s->scal[4]  * wgm_r;
            float wsw = s->scal[10] * wgp_w + s->scal[11] * wgc_w + s->scal[12] * wgm_w;
            wpr = (wsr > 0.f) ? expf(s->scal[5]  * logf(wsr)) : 0.f;
            wpw = (wsw > 0.f) ? expf(s->scal[13] * logf(wsw)) : 0.f;
            s->wpa[nl] = wpr;     // UNNORMALIZED until post-S45
            s->wpb[nl] = wpw;
            if (nl == 0)   { pp->whp_r[0] = wpr; pp->whp_w[0] = wpw; }
            if (nl == 511) { pp->whp_r[1] = wpr; pp->whp_w[1] = wpw; }
        }
        // warp-level z partials; second stage deferred past the read pass
        {
            float zr = wpr, zw = wpw;
#pragma unroll
            for (int o = 16; o; o >>= 1) {
                zr += __shfl_xor_sync(0xffffffffu, zr, o);
                zw += __shfl_xor_sync(0xffffffffu, zw, o);
            }
            if ((t & 31) == 0) s->red[t >> 5] = make_float2(zr, zw);
        }
        __syncthreads();   // publishes wpa/wpb + red

        // ---- read pass with UNNORMALIZED wpa ----
        {
            int n4 = t & 127, mch = t >> 7, wid = t >> 5;
            ulonglong2 wr2 = ((const ulonglong2*)s->wpa)[n4];
#pragma unroll 4
            for (int mi = 0; mi < 8; ++mi) {
                int m = mch * 8 + mi;
                ulonglong2 v2 = memq[m * 128 + n4];
                u64 rp2 = 0ull;
                fma2(rp2, wr2.x, v2.x); fma2(rp2, wr2.y, v2.y);
                float2 rr = up2(rp2);
                float rp = rr.x + rr.y;
#pragma unroll
                for (int o = 16; o; o >>= 1) rp += __shfl_xor_sync(0xffffffffu, rp, o);
                if ((t & 31) == 0) partf[2048 + wid * 8 + mi] = rp;
            }
        }
        __syncthreads();
        if (t < 64) {
            int grp = t >> 3, mi = t & 7;
            float v = partf[2048 + (grp * 4 + 0) * 8 + mi]
                    + partf[2048 + (grp * 4 + 1) * 8 + mi]
                    + partf[2048 + (grp * 4 + 2) * 8 + mi]
                    + partf[2048 + (grp * 4 + 3) * 8 + mi];
#pragma unroll
            for (int i = 0; i < 4; ++i) PP[i]->rrecv[rank][t] = v;
        } else if (t < 96) {
            // finish the z reduce (32 warp partials) and publish to all 4 CTAs
            int l = t - 64;
            float2 z = s->red[l];
#pragma unroll
            for (int o = 16; o; o >>= 1) {
                z.x += __shfl_xor_sync(0xffffffffu, z.x, o);
                z.y += __shfl_xor_sync(0xffffffffu, z.y, o);
            }
            if (l == 0) {
#pragma unroll
                for (int i = 0; i < 4; ++i) PP[i]->zrecv[rank] = z;
            }
        }
        CL_ARRIVE();   // S45 arrive
        if (t < 64) {
            int sn = (step < 63) ? step + 1 : 63;
            xpref = make_float2(x[((bgA << 6) + sn) * 64 + t],
                                x[((bgB << 6) + sn) * 64 + t]);
        }
        CL_WAIT();     // S45: sharpen sums + r partials + boundary wp

        // ---- post-S45: normalize (wpa -> wr), assemble r, stage next inputs ----
        {
            float2 z0 = s->zrecv[0], z1 = s->zrecv[1], z2 = s->zrecv[2], z3 = s->zrecv[3];
            float invZrA = 1.f / ((z0.x + z1.x) + EPS), invZwA = 1.f / ((z0.y + z1.y) + EPS);
            float invZrB = 1.f / ((z2.x + z3.x) + EPS), invZwB = 1.f / ((z2.y + z3.y) + EPS);
            float invZr = (rank < 2) ? invZrA : invZrB;
            float invZw = (rank < 2) ? invZwA : invZwB;
            if (lead) {
                s->wr[nl] = s->wpa[nl] * invZr;
                s->ww[nl] = s->wpb[nl] * invZw;
            }
            if (t == 0) {
                s->wh_r[0] = s->whp_r[0] * invZr; s->wh_r[1] = s->whp_r[1] * invZr;
                s->wh_w[0] = s->whp_w[0] * invZw; s->wh_w[1] = s->whp_w[1] * invZw;
            }
            if (t < 64) {
                float2 rv = make_float2((s->rrecv[0][t] + s->rrecv[1][t]) * invZrA,
                                        (s->rrecv[2][t] + s->rrecv[3][t]) * invZrB);
                s->rvec2[t] = rv;
                s->vh[64 + t] = rv;   s->vh[448 + t] = rv;
                s->vh[t] = xpref;     s->vh[384 + t] = xpref;
            }
        }
        __syncthreads();

        // ---- out: add r-part, reduce, write ----
        {
            float2 rv = s->rvec2[ch8];
            float2 pv = part2[3072 + t];
            pv.x += rv.x * w8b; pv.y += rv.y * w8b;
            part2[3072 + t] = pv;
        }
        __syncthreads();
        if (t < 128) {
            int jc = t & 15, g = t >> 4;
            float2 acc = make_float2(0.f, 0.f);
#pragma unroll
            for (int k = 0; k < 8; ++k) {
                float2 pv = part2[3072 + (g * 8 + k) * 16 + jc];
                acc.x += pv.x; acc.y += pv.y;
            }
            part2[t] = acc;
        }
        __syncthreads();
        if (t < 16) {
            float2 acc = make_float2(bo, bo);
#pragma unroll
            for (int g = 0; g < 8; ++g) {
                float2 pv = part2[g * 16 + t];
                acc.x += pv.x; acc.y += pv.y;
            }
            int col = rank * 16 + t;
            out[((bgA << 6) + step) * 64 + col] = acc.x;
            out[((bgB << 6) + step) * 64 + col] = acc.y;
        }
        __syncthreads();
    }
}

extern "C" void kernel_launch(void* const* d_in, const int* in_sizes, int n_in,
                              void* d_out, int out_size) {
    const float* x      = (const float*)d_in[0];
    const float* Wx     = (const float*)d_in[1];
    const float* Wh     = (const float*)d_in[2];
    const float* b_lstm = (const float*)d_in[3];
    const float* W_head = (const float*)d_in[4];
    const float* b_head = (const float*)d_in[5];
    const float* W_out  = (const float*)d_in[6];
    const float* b_out  = (const float*)d_in[7];
    float* out = (float*)d_out;

    cudaMemcpyToSymbolAsync(g_W, Wx, 128 * 1024 * sizeof(float), 0,
                            cudaMemcpyDeviceToDevice, 0);
    cudaMemcpyToSymbolAsync(g_W, Wh, 256 * 1024 * sizeof(float),
                            128 * 1024 * sizeof(float), cudaMemcpyDeviceToDevice, 0);

    size_t smem = sizeof(SMem);
    cudaFuncSetAttribute(ntm_kernel, cudaFuncAttributeMaxDynamicSharedMemorySize, (int)smem);
    ntm_kernel<<<128, 1024, smem>>>(x, b_lstm, W_head, b_head, W_out, b_out, out);
}